// round 10
// baseline (speedup 1.0000x reference)
#include <cuda_runtime.h>

// Fused: channel-mix (w1) -> double-unfold 1D conv along W (w0, torch-style
// two-stage zero-pad masks) -> roll(+1) along H.
//
// x  : [128, 56, 56] f32, w0 : [32,2,3,3], w1 : [4,64], out : [128,56,56]
//
// out[l*4+p, o, n] = sum_{j,i,k} w0[l,j,i,k] * t4[p,j,(o-1)%56, n+i+k-2]
//                    * [0 <= n+k-1 < 56] * [0 <= n+i+k-2 < 56]
// t4[p,j,h,w] = sum_c w1[p,c] * x[2c+j, h, w]
//
// Combined weights per (l,j), grouped by d=i+k:
//   r0=w(0,0) [t4(n-2), n>=2]   r1=w(0,1)+w(1,0) [t4(n-1), n>=1]
//   r2=w(1,1) [t4(n)]           r3=w(2,0) [t4(n), n>=1]
//   r4=w(0,2) [t4(n), n<=54]    r5=w(1,2)+w(2,1) [t4(n+1), n<=54]
//   r6=w(2,2) [t4(n+2), n<=53]
// Center fold wc = r2+r3+r4; fixups at n=0 (drop r3) and n=55 (drop r4).
//
// Grid 56 (one CTA per output row, best measured shape), block 512.
//   warps 0..13 : stage-1 x staging (float4) + t4 compute
//   warps 14..15: combined-weight prologue (overlaps the x DRAM load)

#define NT 512

__global__ __launch_bounds__(NT, 1) void fused_shuffleconv4(
    const float* __restrict__ x,
    const float* __restrict__ w0,
    const float* __restrict__ w1,
    float* __restrict__ out)
{
    __shared__ float xs[128 * 56];    // full source x row (28672 B)
    __shared__ float t4s[8 * 58];     // rows (p*2+j), stride 58
    __shared__ float wcs[32 * 16];    // combined weights [l][j*7+r], padded to 16

    const int tid  = threadIdx.x;
    const int o    = blockIdx.x;
    const int hsrc = (o + 55) % 56;   // roll(+1): out row o <- y row o-1

    if (tid < 448) {
        // ---- x row staging: 1792 float4 over 448 threads (4 each, coalesced)
        const float* xrow = x + hsrc * 56;
        #pragma unroll
        for (int r = 0; r < 4; r++) {
            int e = tid + r * 448;            // 0..1791
            int c = e / 14, q = e % 14;
            float4 v = *(const float4*)(xrow + c * 3136 + q * 4);
            *(float4*)(xs + c * 56 + q * 4) = v;
        }
    } else {
        // ---- combined weights on warps 14-15 (overlaps x load) ----
        #pragma unroll
        for (int r = 0; r < 7; r++) {
            int e = (tid - 448) * 7 + r;      // 0..447 = 32 l * 14 entries
            int l = e / 14, q = e % 14;
            int j = q / 7,  s = q % 7;
            const float* wb = w0 + (l * 2 + j) * 9;   // [3][3], idx = i*3+k
            float v;
            switch (s) {
                case 0:  v = wb[0];          break;
                case 1:  v = wb[1] + wb[3];  break;
                case 2:  v = wb[4];          break;
                case 3:  v = wb[6];          break;
                case 4:  v = wb[2];          break;
                case 5:  v = wb[5] + wb[7];  break;
                default: v = wb[8];          break;
            }
            wcs[l * 16 + j * 7 + s] = v;
        }
    }
    __syncthreads();

    // ---- stage 1: 448 threads -> 8 (p,j) rows x 56 cols of t4 ----
    if (tid < 448) {
        const int sg = tid / 56;              // p*2+j
        const int n  = tid - sg * 56;
        const int p  = sg >> 1, j = sg & 1;
        const float4* wv = (const float4*)(w1 + p * 64);
        const float*  xb = xs + j * 56 + n;
        float acc = 0.f;
        #pragma unroll
        for (int c4 = 0; c4 < 16; c4++) {
            float4 w4 = __ldg(&wv[c4]);       // uniform per group -> broadcast
            int c = c4 * 4;                   // channel 2c+j -> xs offset c*112
            acc = fmaf(w4.x, xb[(c + 0) * 112], acc);
            acc = fmaf(w4.y, xb[(c + 1) * 112], acc);
            acc = fmaf(w4.z, xb[(c + 2) * 112], acc);
            acc = fmaf(w4.w, xb[(c + 3) * 112], acc);
        }
        t4s[sg * 58 + n] = acc;
    }
    __syncthreads();

    // ---- stage 2: thread = (c_out 0..127, g 0..3) -> 14 outputs ----
    const int c_out = tid >> 2;               // == output channel l*4+p
    const int g     = tid & 3;
    const int l     = c_out >> 2;
    const int p     = c_out & 3;
    const int nbase = g * 14;

    const float* tb0 = t4s + (p * 2) * 58;    // j=0 row
    const float* tb1 = tb0 + 58;              // j=1 row

    float T0[18], T1[18];
    #pragma unroll
    for (int u = 0; u < 18; u++) {
        int gc = nbase - 2 + u;
        int ci = gc < 0 ? 0 : (gc > 55 ? 55 : gc);
        bool ok = (gc >= 0) & (gc <= 55);
        float v0 = tb0[ci], v1 = tb1[ci];
        T0[u] = ok ? v0 : 0.f;
        T1[u] = ok ? v1 : 0.f;
    }

    const float4* wp = (const float4*)(wcs + l * 16);
    float4 A = wp[0];   // j0: r0 r1 r2 r3
    float4 B = wp[1];   // j0: r4 r5 r6 | j1: r0
    float4 C = wp[2];   // j1: r1 r2 r3 r4
    float4 D = wp[3];   // j1: r5 r6 - -
    float wc0 = A.z + A.w + B.x;              // j0 center
    float wc1 = C.y + C.z + C.w;              // j1 center

    float obuf[14];
    #pragma unroll
    for (int i = 0; i < 14; i++) {
        float acc;
        acc = fmaf(A.x, T0[i],     0.f);
        acc = fmaf(A.y, T0[i + 1], acc);
        acc = fmaf(wc0, T0[i + 2], acc);
        acc = fmaf(B.y, T0[i + 3], acc);
        acc = fmaf(B.z, T0[i + 4], acc);
        acc = fmaf(B.w, T1[i],     acc);
        acc = fmaf(C.x, T1[i + 1], acc);
        acc = fmaf(wc1, T1[i + 2], acc);
        acc = fmaf(D.x, T1[i + 3], acc);
        acc = fmaf(D.y, T1[i + 4], acc);
        obuf[i] = acc;
    }
    // edge fixups: n=0 drops r3 from center, n=55 drops r4
    if (g == 0) obuf[0]  -= A.w * T0[2]  + C.z * T1[2];
    if (g == 3) obuf[13] -= B.x * T0[15] + C.w * T1[15];

    float* ob = out + c_out * 3136 + o * 56 + nbase;
    #pragma unroll
    for (int k = 0; k < 7; k++)
        *(float2*)(ob + 2 * k) = make_float2(obuf[2 * k], obuf[2 * k + 1]);
}

extern "C" void kernel_launch(void* const* d_in, const int* in_sizes, int n_in,
                              void* d_out, int out_size) {
    const float* x  = (const float*)d_in[0];
    const float* w0 = (const float*)d_in[1];
    const float* w1 = (const float*)d_in[2];
    float* out = (float*)d_out;
    fused_shuffleconv4<<<56, NT>>>(x, w0, w1, out);
}

// round 12
// speedup vs baseline: 1.0275x; 1.0275x over previous
#include <cuda_runtime.h>

// Fused: channel-mix (w1) -> double-unfold 1D conv along W (w0, torch-style
// two-stage zero-pad masks) -> roll(+1) along H.
//
// x  : [128, 56, 56] f32, w0 : [32,2,3,3], w1 : [4,64], out : [128,56,56]
//
// out[l*4+p, o, n] = sum_{j,i,k} w0[l,j,i,k] * t4[p,j,(o-1)%56, n+i+k-2]
//                    * [0 <= n+k-1 < 56] * [0 <= n+i+k-2 < 56]
// t4[p,j,h,w] = sum_c w1[p,c] * x[2c+j, h, w]
//
// Combined weights per (l,j), grouped by d=i+k:
//   r0=w(0,0) [t4(n-2), n>=2]   r1=w(0,1)+w(1,0) [t4(n-1), n>=1]
//   r2=w(1,1) [t4(n)]           r3=w(2,0) [t4(n), n>=1]
//   r4=w(0,2) [t4(n), n<=54]    r5=w(1,2)+w(2,1) [t4(n+1), n<=54]
//   r6=w(2,2) [t4(n+2), n<=53]
// Center fold wc = r2+r3+r4; fixups at n=0 (drop r3) and n=55 (drop r4).
//
// Grid 56 (one CTA per output row), block 512:
//   prologue: warps 0-13 stage the x row (float4); warps 14-15 stage w1 and
//             build combined weights — NO global loads after the barrier.
//   stage 1 : 224 threads, float2-vectorized t4 (2 n-values/thread).
//   stage 2 : 512 threads = (c_out, quarter), register-resident 5-tap conv.

#define NT 512

__global__ __launch_bounds__(NT, 1) void fused_shuffleconv5(
    const float* __restrict__ x,
    const float* __restrict__ w0,
    const float* __restrict__ w1,
    float* __restrict__ out)
{
    __shared__ float xs[128 * 56];    // full source x row (28672 B)
    __shared__ float t4s[8 * 58];     // rows (p*2+j), stride 58
    __shared__ float w1s[256];        // w1 [4][64]
    __shared__ float wcs[32 * 16];    // combined weights [l][j*7+r], padded to 16

    const int tid  = threadIdx.x;
    const int o    = blockIdx.x;
    const int hsrc = (o + 55) % 56;   // roll(+1): out row o <- y row o-1

    if (tid < 448) {
        // ---- x row staging: 1792 float4 over 448 threads (4 each, coalesced)
        const float* xrow = x + hsrc * 56;
        #pragma unroll
        for (int r = 0; r < 4; r++) {
            int e = tid + r * 448;            // 0..1791
            int c = e / 14, q = e % 14;
            float4 v = *(const float4*)(xrow + c * 3136 + q * 4);
            *(float4*)(xs + c * 56 + q * 4) = v;
        }
    } else {
        // ---- warps 14-15: w1 -> smem (float4 each) + combined weights ----
        int u = tid - 448;                    // 0..63
        ((float4*)w1s)[u] = ((const float4*)w1)[u];
        #pragma unroll
        for (int r = 0; r < 7; r++) {
            int e = u * 7 + r;                // 0..447 = 32 l * 14 entries
            int l = e / 14, q = e % 14;
            int j = q / 7,  s = q % 7;
            const float* wb = w0 + (l * 2 + j) * 9;   // [3][3], idx = i*3+k
            float v;
            switch (s) {
                case 0:  v = wb[0];          break;
                case 1:  v = wb[1] + wb[3];  break;
                case 2:  v = wb[4];          break;
                case 3:  v = wb[6];          break;
                case 4:  v = wb[2];          break;
                case 5:  v = wb[5] + wb[7];  break;
                default: v = wb[8];          break;
            }
            wcs[l * 16 + j * 7 + s] = v;
        }
    }
    __syncthreads();

    // ---- stage 1: 224 threads -> 8 (p,j) rows x 28 n-pairs of t4 ----
    if (tid < 224) {
        const int sg = tid / 28;              // p*2+j
        const int n  = (tid - sg * 28) * 2;
        const int p  = sg >> 1, j = sg & 1;
        const float4* wv = (const float4*)(w1s + p * 64);   // smem broadcast
        const float*  xb = xs + j * 56 + n;
        float a0 = 0.f, a1 = 0.f;
        #pragma unroll
        for (int c4 = 0; c4 < 16; c4++) {
            float4 w4 = wv[c4];
            int c = c4 * 4;                   // channel 2c+j -> xs offset c*112
            float2 v0 = *(const float2*)(xb + (c + 0) * 112);
            float2 v1 = *(const float2*)(xb + (c + 1) * 112);
            float2 v2 = *(const float2*)(xb + (c + 2) * 112);
            float2 v3 = *(const float2*)(xb + (c + 3) * 112);
            a0 = fmaf(w4.x, v0.x, a0);  a1 = fmaf(w4.x, v0.y, a1);
            a0 = fmaf(w4.y, v1.x, a0);  a1 = fmaf(w4.y, v1.y, a1);
            a0 = fmaf(w4.z, v2.x, a0);  a1 = fmaf(w4.z, v2.y, a1);
            a0 = fmaf(w4.w, v3.x, a0);  a1 = fmaf(w4.w, v3.y, a1);
        }
        *(float2*)(t4s + sg * 58 + n) = make_float2(a0, a1);
    }
    __syncthreads();

    // ---- stage 2: thread = (c_out 0..127, g 0..3) -> 14 outputs ----
    const int c_out = tid >> 2;               // output channel l*4+p
    const int g     = tid & 3;
    const int l     = c_out >> 2;
    const int p     = c_out & 3;
    const int nbase = g * 14;

    const float* tb0 = t4s + (p * 2) * 58;    // j=0 row
    const float* tb1 = tb0 + 58;              // j=1 row

    float T0[18], T1[18];
    #pragma unroll
    for (int u = 0; u < 18; u++) {
        int gc = nbase - 2 + u;
        int ci = gc < 0 ? 0 : (gc > 55 ? 55 : gc);
        bool ok = (gc >= 0) & (gc <= 55);
        float v0 = tb0[ci], v1 = tb1[ci];
        T0[u] = ok ? v0 : 0.f;
        T1[u] = ok ? v1 : 0.f;
    }

    const float4* wp = (const float4*)(wcs + l * 16);
    float4 A = wp[0];   // j0: r0 r1 r2 r3
    float4 B = wp[1];   // j0: r4 r5 r6 | j1: r0
    float4 C = wp[2];   // j1: r1 r2 r3 r4
    float4 D = wp[3];   // j1: r5 r6 - -
    float wc0 = A.z + A.w + B.x;              // j0 center
    float wc1 = C.y + C.z + C.w;              // j1 center

    float obuf[14];
    #pragma unroll
    for (int i = 0; i < 14; i++) {
        float acc;
        acc = fmaf(A.x, T0[i],     0.f);
        acc = fmaf(A.y, T0[i + 1], acc);
        acc = fmaf(wc0, T0[i + 2], acc);
        acc = fmaf(B.y, T0[i + 3], acc);
        acc = fmaf(B.z, T0[i + 4], acc);
        acc = fmaf(B.w, T1[i],     acc);
        acc = fmaf(C.x, T1[i + 1], acc);
        acc = fmaf(wc1, T1[i + 2], acc);
        acc = fmaf(D.x, T1[i + 3], acc);
        acc = fmaf(D.y, T1[i + 4], acc);
        obuf[i] = acc;
    }
    // edge fixups: n=0 drops r3 from center, n=55 drops r4
    if (g == 0) obuf[0]  -= A.w * T0[2]  + C.z * T1[2];
    if (g == 3) obuf[13] -= B.x * T0[15] + C.w * T1[15];

    float* ob = out + c_out * 3136 + o * 56 + nbase;
    #pragma unroll
    for (int k = 0; k < 7; k++)
        *(float2*)(ob + 2 * k) = make_float2(obuf[2 * k], obuf[2 * k + 1]);
}

extern "C" void kernel_launch(void* const* d_in, const int* in_sizes, int n_in,
                              void* d_out, int out_size) {
    const float* x  = (const float*)d_in[0];
    const float* w0 = (const float*)d_in[1];
    const float* w1 = (const float*)d_in[2];
    float* out = (float*)d_out;
    fused_shuffleconv5<<<56, NT>>>(x, w0, w1, out);
}

// round 13
// speedup vs baseline: 1.0435x; 1.0155x over previous
#include <cuda_runtime.h>

// Fused: channel-mix (w1) -> double-unfold 1D conv along W (w0, torch-style
// two-stage zero-pad masks) -> roll(+1) along H.
//
// x  : [128, 56, 56] f32, w0 : [32,2,3,3], w1 : [4,64], out : [128,56,56]
//
// out[l*4+p, o, n] = sum_{j,i,k} w0[l,j,i,k] * t4[p,j,(o-1)%56, n+i+k-2]
//                    * [0 <= n+k-1 < 56] * [0 <= n+i+k-2 < 56]
// t4[p,j,h,w] = sum_c w1[p,c] * x[2c+j, h, w]
//
// Combined weights per (l,j) grouped by d=i+k (r0..r6 as in prior rounds);
// center fold wc = r2+r3+r4 with fixups at n=0 (drop r3) and n=55 (drop r4).
//
// Grid 224 = 56 rows x 4 p. Block 128. ONE barrier:
//   [wcs build || stage1: direct LDG x, 4-accumulator dot] -> bar ->
//   [stage2: register 5-tap conv, 32 l x 4 quarters] -> STG.

#define NT 128

__global__ __launch_bounds__(NT, 4) void fused_shuffleconv6(
    const float* __restrict__ x,
    const float* __restrict__ w0,
    const float* __restrict__ w1,
    float* __restrict__ out)
{
    __shared__ float t4s[2 * 58];     // rows j=0,1 for this CTA's p; stride 58
    __shared__ float wcs[32 * 20];    // combined weights [l][j*7+r], stride 20

    const int tid  = threadIdx.x;
    const int o    = blockIdx.x >> 2;
    const int p    = blockIdx.x & 3;
    const int hsrc = (o + 55) % 56;   // roll(+1): out row o <- y row o-1

    // ---- combined weights: 448 entries over 128 threads (independent LDGs,
    //      overlap the stage-1 x loads below) ----
    #pragma unroll
    for (int e = tid; e < 448; e += NT) {
        int l = e / 14, q = e % 14;
        int j = q / 7,  s = q % 7;
        const float* wb = w0 + (l * 2 + j) * 9;   // [3][3], idx = i*3+k
        float v;
        switch (s) {
            case 0:  v = wb[0];          break;
            case 1:  v = wb[1] + wb[3];  break;
            case 2:  v = wb[4];          break;
            case 3:  v = wb[6];          break;
            case 4:  v = wb[2];          break;
            case 5:  v = wb[5] + wb[7];  break;
            default: v = wb[8];          break;
        }
        wcs[l * 20 + j * 7 + s] = v;
    }

    // ---- stage 1: threads 0..111 = (j, m) -> t4[p,j,m], 4 accumulators ----
    if (tid < 112) {
        const int j = tid / 56;
        const int m = tid - j * 56;
        const float*  xb  = x + j * 3136 + hsrc * 56 + m;   // + c*6272 per c
        const float4* wv4 = (const float4*)(w1 + p * 64);
        float a0 = 0.f, a1 = 0.f, a2 = 0.f, a3 = 0.f;
        #pragma unroll
        for (int c8 = 0; c8 < 8; c8++) {
            float4 wA = __ldg(wv4 + c8 * 2);
            float4 wB = __ldg(wv4 + c8 * 2 + 1);
            const float* xc = xb + c8 * 8 * 6272;
            float x0 = xc[0 * 6272], x1 = xc[1 * 6272];
            float x2 = xc[2 * 6272], x3 = xc[3 * 6272];
            float x4 = xc[4 * 6272], x5 = xc[5 * 6272];
            float x6 = xc[6 * 6272], x7 = xc[7 * 6272];
            a0 = fmaf(wA.x, x0, a0);
            a1 = fmaf(wA.y, x1, a1);
            a2 = fmaf(wA.z, x2, a2);
            a3 = fmaf(wA.w, x3, a3);
            a0 = fmaf(wB.x, x4, a0);
            a1 = fmaf(wB.y, x5, a1);
            a2 = fmaf(wB.z, x6, a2);
            a3 = fmaf(wB.w, x7, a3);
        }
        t4s[j * 58 + m] = (a0 + a1) + (a2 + a3);
    }
    __syncthreads();

    // ---- stage 2: thread = (l 0..31, g 0..3) -> 14 outputs ----
    const int l     = tid >> 2;
    const int g     = tid & 3;
    const int nbase = g * 14;

    const float* tb0 = t4s;           // j=0 row
    const float* tb1 = t4s + 58;      // j=1 row

    float T0[18], T1[18];
    #pragma unroll
    for (int u = 0; u < 18; u++) {
        int gc = nbase - 2 + u;
        int ci = gc < 0 ? 0 : (gc > 55 ? 55 : gc);
        bool ok = (gc >= 0) & (gc <= 55);
        float v0 = tb0[ci], v1 = tb1[ci];
        T0[u] = ok ? v0 : 0.f;
        T1[u] = ok ? v1 : 0.f;
    }

    const float4* wp = (const float4*)(wcs + l * 20);
    float4 A = wp[0];   // j0: r0 r1 r2 r3
    float4 B = wp[1];   // j0: r4 r5 r6 | j1: r0
    float4 C = wp[2];   // j1: r1 r2 r3 r4
    float4 D = wp[3];   // j1: r5 r6 - -
    float wc0 = A.z + A.w + B.x;      // j0 center
    float wc1 = C.y + C.z + C.w;      // j1 center

    float obuf[14];
    #pragma unroll
    for (int i = 0; i < 14; i++) {
        float acc0, acc1;
        acc0 = fmaf(A.x, T0[i],     0.f);
        acc1 = fmaf(A.y, T0[i + 1], 0.f);
        acc0 = fmaf(wc0, T0[i + 2], acc0);
        acc1 = fmaf(B.y, T0[i + 3], acc1);
        acc0 = fmaf(B.z, T0[i + 4], acc0);
        acc1 = fmaf(B.w, T1[i],     acc1);
        acc0 = fmaf(C.x, T1[i + 1], acc0);
        acc1 = fmaf(wc1, T1[i + 2], acc1);
        acc0 = fmaf(D.x, T1[i + 3], acc0);
        acc1 = fmaf(D.y, T1[i + 4], acc1);
        obuf[i] = acc0 + acc1;
    }
    // edge fixups: n=0 drops r3 from center, n=55 drops r4
    if (g == 0) obuf[0]  -= A.w * T0[2]  + C.z * T1[2];
    if (g == 3) obuf[13] -= B.x * T0[15] + C.w * T1[15];

    float* ob = out + (l * 4 + p) * 3136 + o * 56 + nbase;
    #pragma unroll
    for (int k = 0; k < 7; k++)
        *(float2*)(ob + 2 * k) = make_float2(obuf[2 * k], obuf[2 * k + 1]);
}

extern "C" void kernel_launch(void* const* d_in, const int* in_sizes, int n_in,
                              void* d_out, int out_size) {
    const float* x  = (const float*)d_in[0];
    const float* w0 = (const float*)d_in[1];
    const float* w1 = (const float*)d_in[2];
    float* out = (float*)d_out;
    fused_shuffleconv6<<<224, NT>>>(x, w0, w1, out);
}

// round 17
// speedup vs baseline: 1.2399x; 1.1882x over previous
#include <cuda_runtime.h>

// Fused: channel-mix (w1) -> double-unfold 1D conv along W (w0, torch-style
// two-stage zero-pad masks) -> roll(+1) along H.
//
// x  : [128, 56, 56] f32, w0 : [32,2,3,3], w1 : [4,64], out : [128,56,56]
//
// out[l*4+p, o, n] = sum_{j,i,k} w0[l,j,i,k] * t4[p,j,(o-1)%56, n+i+k-2]
//                    * [0 <= n+k-1 < 56] * [0 <= n+i+k-2 < 56]
// t4[p,j,h,w] = sum_c w1[p,c] * x[2c+j, h, w]
//
// Combined weights per (l,j) grouped by d=i+k:
//   r0=w(0,0)[n-2]  r1=w(0,1)+w(1,0)[n-1]  wc=r2+r3+r4[n]
//   r5=w(1,2)+w(2,1)[n+1]  r6=w(2,2)[n+2];  fixups at n=0 (-r3), n=55 (-r4).
//
// R1 shape (grid 56, block 448, staged float4 x) with restructured stage 2:
// thread = (channel-pair, 8-col strip); the pair shares l -> ONE weight set
// (4 LDS.128) instead of 16 sets; float4 stores.

#define NT 448

__global__ __launch_bounds__(NT, 1) void fused_shuffleconv7(
    const float* __restrict__ x,
    const float* __restrict__ w0,
    const float* __restrict__ w1,
    float* __restrict__ out)
{
    __shared__ float xs[128 * 56];    // source x row (28672 B)
    __shared__ float t4s[8 * 58];     // rows (p*2+j), stride 58
    __shared__ float w1s[256];        // w1 [4][64]
    __shared__ float wcs[32 * 16];    // combined weights [l][j*7+r], padded

    const int tid  = threadIdx.x;
    const int o    = blockIdx.x;
    const int hsrc = (o + 55) % 56;   // roll(+1): out row o <- y row o-1

    // ---- prologue (R1-style, interleaved independent loads) ----
    if (tid < 256) w1s[tid] = w1[tid];

    {   // 448 threads -> 32*14 combined-weight entries
        int l = tid / 14, q = tid % 14;
        int j = q / 7,    r = q % 7;
        const float* wb = w0 + (l * 2 + j) * 9;   // [3][3], idx = i*3+k
        float v;
        switch (r) {
            case 0:  v = wb[0];          break;
            case 1:  v = wb[1] + wb[3];  break;
            case 2:  v = wb[4];          break;
            case 3:  v = wb[6];          break;
            case 4:  v = wb[2];          break;
            case 5:  v = wb[5] + wb[7];  break;
            default: v = wb[8];          break;
        }
        wcs[l * 16 + j * 7 + r] = v;
    }

    // x row: 1792 float4 over 448 threads (coalesced)
    #pragma unroll
    for (int r = 0; r < 4; r++) {
        int e = tid + r * 448;
        int c = e / 14, q = e % 14;
        float4 v = *(const float4*)(x + c * 3136 + hsrc * 56 + q * 4);
        *(float4*)(xs + c * 56 + q * 4) = v;
    }
    __syncthreads();

    // ---- stage 1: (sg, n) -> t4[p,j,n]; dual accumulators ----
    {
        const int sg = tid / 56;              // p*2+j
        const int n  = tid - sg * 56;
        const int p  = sg >> 1, j = sg & 1;
        const float4* wv = (const float4*)(w1s + p * 64);
        const float*  xb = xs + j * 56 + n;
        float a0 = 0.f, a1 = 0.f;
        #pragma unroll
        for (int c4 = 0; c4 < 16; c4++) {
            float4 w4 = wv[c4];
            int c = c4 * 4;                   // channel 2c+j -> xs offset c*112
            a0 = fmaf(w4.x, xb[(c + 0) * 112], a0);
            a1 = fmaf(w4.y, xb[(c + 1) * 112], a1);
            a0 = fmaf(w4.z, xb[(c + 2) * 112], a0);
            a1 = fmaf(w4.w, xb[(c + 3) * 112], a1);
        }
        t4s[sg * 58 + n] = a0 + a1;
    }
    __syncthreads();

    // ---- stage 2: thread = (channel-pair cp, strip s) -> 2 ch x 8 cols ----
    const int cp    = tid / 7;                // 0..63
    const int s     = tid - cp * 7;           // 0..6
    const int l     = cp >> 1;                // both channels share l
    const int nbase = s * 8;

    const float4* wp = (const float4*)(wcs + l * 16);
    float4 A = wp[0];   // j0: r0 r1 r2 r3
    float4 B = wp[1];   // j0: r4 r5 r6 | j1: r0
    float4 C = wp[2];   // j1: r1 r2 r3 r4
    float4 D = wp[3];   // j1: r5 r6 - -
    const float wc0 = A.z + A.w + B.x;        // j0 center
    const float wc1 = C.y + C.z + C.w;        // j1 center

    #pragma unroll
    for (int h = 0; h < 2; h++) {
        const int c_out = cp * 2 + h;
        const int p     = c_out & 3;
        const float* tb0 = t4s + (p * 2) * 58;    // j=0 row
        const float* tb1 = tb0 + 58;              // j=1 row

        float T0[12], T1[12];
        #pragma unroll
        for (int u = 0; u < 12; u++) {
            int gc = nbase - 2 + u;
            int ci = gc < 0 ? 0 : (gc > 55 ? 55 : gc);
            bool ok = (gc >= 0) & (gc <= 55);
            float v0 = tb0[ci], v1 = tb1[ci];
            T0[u] = ok ? v0 : 0.f;
            T1[u] = ok ? v1 : 0.f;
        }

        float obuf[8];
        #pragma unroll
        for (int i = 0; i < 8; i++) {
            float acc0, acc1;
            acc0 = fmaf(A.x, T0[i],     0.f);
            acc1 = fmaf(A.y, T0[i + 1], 0.f);
            acc0 = fmaf(wc0, T0[i + 2], acc0);
            acc1 = fmaf(B.y, T0[i + 3], acc1);
            acc0 = fmaf(B.z, T0[i + 4], acc0);
            acc1 = fmaf(B.w, T1[i],     acc1);
            acc0 = fmaf(C.x, T1[i + 1], acc0);
            acc1 = fmaf(wc1, T1[i + 2], acc1);
            acc0 = fmaf(D.x, T1[i + 3], acc0);
            acc1 = fmaf(D.y, T1[i + 4], acc1);
            obuf[i] = acc0 + acc1;
        }
        // edge fixups: n=0 drops r3 from center, n=55 drops r4
        if (s == 0) obuf[0] -= A.w * T0[2] + C.z * T1[2];
        if (s == 6) obuf[7] -= B.x * T0[9] + C.w * T1[9];

        float* ob = out + c_out * 3136 + o * 56 + nbase;
        *(float4*)(ob)     = make_float4(obuf[0], obuf[1], obuf[2], obuf[3]);
        *(float4*)(ob + 4) = make_float4(obuf[4], obuf[5], obuf[6], obuf[7]);
    }
}

extern "C" void kernel_launch(void* const* d_in, const int* in_sizes, int n_in,
                              void* d_out, int out_size) {
    const float* x  = (const float*)d_in[0];
    const float* w0 = (const float*)d_in[1];
    const float* w1 = (const float*)d_in[2];
    float* out = (float*)d_out;
    fused_shuffleconv7<<<56, NT>>>(x, w0, w1, out);
}